// round 6
// baseline (speedup 1.0000x reference)
#include <cuda_runtime.h>

// metaCLF_20504173871859 — fused per-voxel MLP filter kernel.
// out[b,p] = sum_c x[b,c,p] * (G3 @ relu(G2 @ relu(G1 @ kron3(encode(dx),encode(dy),encode(dz)))))_c
//
// Strategy (round 1): one voxel per thread, all weights in __constant__
// (warp-uniform LDCU operands on the uniform port so the FFMA pipe keeps its
// rt=2 cadence), last two layers fused with the output dot so only
// h1[32] + x[32] stay live in registers.

#define IN_CS 32
#define NVOX  (96 * 96 * 96)   // 884736 voxels per batch (problem-fixed shape)

__constant__ float cW1[16 * 2];    // [16][2]   row-major
__constant__ float cW2[3 * 16];    // [3][16]
__constant__ float cG1[32 * 27];   // [32][27]
__constant__ float cG2[64 * 32];   // [64][32]
__constant__ float cG3[32 * 64];   // [32][64]

__device__ __forceinline__ void encode2(float a, float b, float out3[3]) {
    // W2 @ relu(W1 @ [a,b])
    float h[16];
#pragma unroll
    for (int i = 0; i < 16; ++i)
        h[i] = fmaxf(fmaf(cW1[2 * i], a, cW1[2 * i + 1] * b), 0.0f);
#pragma unroll
    for (int j = 0; j < 3; ++j) {
        float s = 0.0f;
#pragma unroll
        for (int i = 0; i < 16; ++i)
            s = fmaf(cW2[16 * j + i], h[i], s);
        out3[j] = s;
    }
}

__global__ __launch_bounds__(256)
void fused_filter_kernel(const float* __restrict__ x,
                         const float* __restrict__ d_all,
                         float* __restrict__ out,
                         int total)
{
    int v = blockIdx.x * blockDim.x + threadIdx.x;
    if (v >= total) return;

    const int nvox = NVOX;
    int b = v / nvox;            // batch index (0 or 1)
    int p = v - b * nvox;        // voxel index within batch

    const float* xb = x     + (size_t)b * IN_CS * nvox + p;
    const float* db = d_all + (size_t)b * 6     * nvox + p;

    // ---- encode the three directional pairs -> xx, yy, zz (3 each) ----
    float xx[3], yy[3], zz[3];
    {
        float d0 = db[0];
        float d1 = db[(size_t)1 * nvox];
        float d2 = db[(size_t)2 * nvox];
        float d3 = db[(size_t)3 * nvox];
        float d4 = db[(size_t)4 * nvox];
        float d5 = db[(size_t)5 * nvox];
        encode2(d0, d1, xx);
        encode2(d2, d3, yy);
        encode2(d4, d5, zz);
    }

    // ---- enced = kron(kron(xx, yy), zz): enc[i*9 + j*3 + k] ----
    float enc[27];
#pragma unroll
    for (int i = 0; i < 3; ++i) {
#pragma unroll
        for (int j = 0; j < 3; ++j) {
            float pij = xx[i] * yy[j];
#pragma unroll
            for (int k = 0; k < 3; ++k)
                enc[i * 9 + j * 3 + k] = pij * zz[k];
        }
    }

    // ---- h1 = relu(G1 @ enc)  [32] ----
    float h1[32];
#pragma unroll
    for (int c = 0; c < 32; ++c) {
        float s = 0.0f;
#pragma unroll
        for (int j = 0; j < 27; ++j)
            s = fmaf(cG1[27 * c + j], enc[j], s);
        h1[c] = fmaxf(s, 0.0f);
    }

    // ---- load x channels (coalesced: threads contiguous in p) ----
    float xr[32];
#pragma unroll
    for (int c = 0; c < 32; ++c)
        xr[c] = xb[(size_t)c * nvox];

    // ---- fused: out = sum_k relu(G2[k,:]·h1) * (sum_c x_c G3[c,k]) ----
    float acc = 0.0f;
#pragma unroll 8
    for (int k = 0; k < 64; ++k) {
        float s2 = 0.0f;   // (G2 @ h1)_k
        float t  = 0.0f;   // (x^T G3)_k
#pragma unroll
        for (int c = 0; c < 32; ++c) {
            s2 = fmaf(cG2[32 * k + c], h1[c], s2);
            t  = fmaf(cG3[64 * c + k], xr[c], t);
        }
        acc = fmaf(fmaxf(s2, 0.0f), t, acc);
    }

    out[v] = acc;   // out index == b*nvox + p == v
}

extern "C" void kernel_launch(void* const* d_in, const int* in_sizes, int n_in,
                              void* d_out, int out_size)
{
    const float* x     = (const float*)d_in[0];
    const float* d_all = (const float*)d_in[1];

    // Stage weights into constant memory (D2D async memcpy nodes: graph-capturable,
    // no allocation). Sizes are problem-fixed.
    cudaMemcpyToSymbolAsync(cW1, d_in[2], sizeof(float) * 16 * 2,  0, cudaMemcpyDeviceToDevice, 0);
    cudaMemcpyToSymbolAsync(cW2, d_in[3], sizeof(float) * 3 * 16,  0, cudaMemcpyDeviceToDevice, 0);
    cudaMemcpyToSymbolAsync(cG1, d_in[4], sizeof(float) * 32 * 27, 0, cudaMemcpyDeviceToDevice, 0);
    cudaMemcpyToSymbolAsync(cG2, d_in[5], sizeof(float) * 64 * 32, 0, cudaMemcpyDeviceToDevice, 0);
    cudaMemcpyToSymbolAsync(cG3, d_in[6], sizeof(float) * 32 * 64, 0, cudaMemcpyDeviceToDevice, 0);

    int total = out_size;            // B * H*W*D = 2 * 96^3 = 1,769,472
    int threads = 256;
    int blocks = (total + threads - 1) / threads;
    fused_filter_kernel<<<blocks, threads>>>(x, d_all, (float*)d_out, total);
}

// round 9
// speedup vs baseline: 1.3445x; 1.3445x over previous
#include <cuda_runtime.h>

// metaCLF_20504173871859 — round 7: packed f32x2 (2 voxels/thread) + pre-duplicated
// constant weights (one LDCU.64 per weight feeds a 2-voxel fma.rn.f32x2).
//
// Per-voxel math: out = sum_c x_c * (G3 @ relu(G2 @ relu(G1 @ kron3(enc(dx),enc(dy),enc(dz)))))_c
// Last two layers fused with the output dot (no filters[] materialization).

#define IN_CS 32
#define NVOX  (96 * 96 * 96)          // 884736 voxels per batch
#define HPAIR (NVOX / 2)              // voxel pairs per batch

typedef unsigned long long u64;

// Packed-weight constant layout (each weight stored duplicated (w,w)):
//   [0,32)      W1[i][0..1]  as i*2+{0,1}
//   [32,80)     W2[j][i]     as 32 + j*16+i
//   [80,944)    G1[c][j]     as 80 + c*27+j
//   [944,2992)  G2[k][c]     as 944 + k*32+c
//   [2992,5040) G3t[k][c] = G3[c][k]   as 2992 + k*32+c   (pre-transposed)
#define OFF_W1 0
#define OFF_W2 32
#define OFF_G1 80
#define OFF_G2 944
#define OFF_G3 2992
#define NPACK  5040

__constant__ float2 cPack[NPACK];          // 40,320 bytes
__device__  float2 g_packbuf[NPACK];       // prep scratch (no allocation)

// ---------------- packed f32x2 helpers ----------------
__device__ __forceinline__ u64 fma2(u64 a, u64 b, u64 c) {
    u64 d;
    asm("fma.rn.f32x2 %0, %1, %2, %3;" : "=l"(d) : "l"(a), "l"(b), "l"(c));
    return d;
}
__device__ __forceinline__ u64 mul2(u64 a, u64 b) {
    u64 d;
    asm("mul.rn.f32x2 %0, %1, %2;" : "=l"(d) : "l"(a), "l"(b));
    return d;
}
__device__ __forceinline__ u64 relu2(u64 v) {
    float lo, hi;
    asm("mov.b64 {%0, %1}, %2;" : "=f"(lo), "=f"(hi) : "l"(v));
    lo = fmaxf(lo, 0.0f);
    hi = fmaxf(hi, 0.0f);
    u64 r;
    asm("mov.b64 %0, {%1, %2};" : "=l"(r) : "f"(lo), "f"(hi));
    return r;
}
// duplicated weight pair from constant memory (compile-time index -> LDCU.64)
__device__ __forceinline__ u64 CP(int i) {
    return *reinterpret_cast<const u64*>(cPack + i);
}

// ---------------- prep: duplicate + reorder weights ----------------
__global__ void pack_weights_kernel(const float* __restrict__ W1,
                                    const float* __restrict__ W2,
                                    const float* __restrict__ G1,
                                    const float* __restrict__ G2,
                                    const float* __restrict__ G3)
{
    for (int i = threadIdx.x; i < NPACK; i += blockDim.x) {
        float w;
        if (i < OFF_W2) {                      // W1 [16][2], kept in row order
            w = W1[i - OFF_W1];
        } else if (i < OFF_G1) {               // W2 [3][16]
            w = W2[i - OFF_W2];
        } else if (i < OFF_G2) {               // G1 [32][27]
            w = G1[i - OFF_G1];
        } else if (i < OFF_G3) {               // G2 [64][32]
            w = G2[i - OFF_G2];
        } else {                               // G3t[k][c] = G3[c][k], G3 is [32][64]
            int t = i - OFF_G3;
            int k = t >> 5;                    // 0..63
            int c = t & 31;                    // 0..31
            w = G3[c * 64 + k];
        }
        g_packbuf[i] = make_float2(w, w);
    }
}

// ---------------- packed encode: W2 @ relu(W1 @ [a,b]) ----------------
__device__ __forceinline__ void encode2p(u64 a, u64 b, u64 o[3]) {
    u64 h[16];
#pragma unroll
    for (int i = 0; i < 16; ++i)
        h[i] = relu2(fma2(CP(OFF_W1 + 2 * i), a, mul2(CP(OFF_W1 + 2 * i + 1), b)));
#pragma unroll
    for (int j = 0; j < 3; ++j) {
        u64 s = mul2(CP(OFF_W2 + 16 * j), h[0]);
#pragma unroll
        for (int i = 1; i < 16; ++i)
            s = fma2(CP(OFF_W2 + 16 * j + i), h[i], s);
        o[j] = s;
    }
}

__global__ __launch_bounds__(128, 2)
void fused_filter2_kernel(const u64* __restrict__ x2,
                          const u64* __restrict__ d2,
                          u64* __restrict__ out2,
                          int npairs)
{
    int q = blockIdx.x * blockDim.x + threadIdx.x;
    if (q >= npairs) return;

    int b = q / HPAIR;                 // batch (0 or 1); pairs never straddle batches
    int p = q - b * HPAIR;

    const u64* xb = x2 + (size_t)b * IN_CS * HPAIR + p;   // channel stride HPAIR
    const u64* db = d2 + (size_t)b * 6     * HPAIR + p;

    // ---- encode the three directional pairs ----
    u64 xx[3], yy[3], zz[3];
    {
        u64 d0 = db[0];
        u64 d1 = db[(size_t)1 * HPAIR];
        u64 d2v = db[(size_t)2 * HPAIR];
        u64 d3 = db[(size_t)3 * HPAIR];
        u64 d4 = db[(size_t)4 * HPAIR];
        u64 d5 = db[(size_t)5 * HPAIR];
        encode2p(d0, d1, xx);
        encode2p(d2v, d3, yy);
        encode2p(d4, d5, zz);
    }

    // ---- enc = kron(kron(xx,yy),zz) : enc[i*9+j*3+k] ----
    u64 enc[27];
#pragma unroll
    for (int i = 0; i < 3; ++i) {
#pragma unroll
        for (int j = 0; j < 3; ++j) {
            u64 pij = mul2(xx[i], yy[j]);
#pragma unroll
            for (int k = 0; k < 3; ++k)
                enc[i * 9 + j * 3 + k] = mul2(pij, zz[k]);
        }
    }

    // ---- h1 = relu(G1 @ enc) [32] ----
    u64 h1[32];
#pragma unroll
    for (int c = 0; c < 32; ++c) {
        u64 s = mul2(CP(OFF_G1 + 27 * c), enc[0]);
#pragma unroll
        for (int j = 1; j < 27; ++j)
            s = fma2(CP(OFF_G1 + 27 * c + j), enc[j], s);
        h1[c] = relu2(s);
    }

    // ---- load x channels (8B coalesced, voxel pair contiguous) ----
    u64 xr[32];
#pragma unroll
    for (int c = 0; c < 32; ++c)
        xr[c] = xb[(size_t)c * HPAIR];

    // ---- fused G2/G3/output: out = sum_k relu(G2[k]·h1) * (G3t[k]·x) ----
    u64 acc = 0ull;   // packed (0.0f, 0.0f)
#pragma unroll 8
    for (int k = 0; k < 64; ++k) {
        u64 s2 = mul2(CP(OFF_G2 + 32 * k), h1[0]);
        u64 t  = mul2(CP(OFF_G3 + 32 * k), xr[0]);
#pragma unroll
        for (int c = 1; c < 32; ++c) {
            s2 = fma2(CP(OFF_G2 + 32 * k + c), h1[c], s2);
            t  = fma2(CP(OFF_G3 + 32 * k + c), xr[c], t);
        }
        acc = fma2(relu2(s2), t, acc);
    }

    out2[q] = acc;
}

extern "C" void kernel_launch(void* const* d_in, const int* in_sizes, int n_in,
                              void* d_out, int out_size)
{
    const float* x     = (const float*)d_in[0];
    const float* d_all = (const float*)d_in[1];

    // 1) duplicate/reorder weights into device scratch (single small block)
    pack_weights_kernel<<<1, 256>>>((const float*)d_in[2], (const float*)d_in[3],
                                    (const float*)d_in[4], (const float*)d_in[5],
                                    (const float*)d_in[6]);

    // 2) move scratch into constant bank (D2D memcpy node — graph-capturable)
    void* psrc = nullptr;
    cudaGetSymbolAddress(&psrc, g_packbuf);
    cudaMemcpyToSymbolAsync(cPack, psrc, sizeof(float2) * NPACK, 0,
                            cudaMemcpyDeviceToDevice, 0);

    // 3) main fused kernel, 2 voxels per thread
    int npairs  = out_size / 2;        // 884,736
    int threads = 128;
    int blocks  = (npairs + threads - 1) / threads;
    fused_filter2_kernel<<<blocks, threads>>>((const u64*)x, (const u64*)d_all,
                                              (u64*)d_out, npairs);
}